// round 1
// baseline (speedup 1.0000x reference)
#include <cuda_runtime.h>

#define NB 32
#define NT 8192
#define NC 1024
#define NH 16
#define SCALE 0.03125f   // 1024^-0.5

// ---- scratch (allocation-free rule: __device__ globals) ----
__device__ float g_scores[(size_t)NB * NT * NH];   // 16.8 MB
__device__ float g_Z[NB * NH];
__device__ float g_pooled[NB * NC];

// ---- packed fp32x2 helpers (Blackwell) ----
__device__ __forceinline__ void ffma2(unsigned long long& d,
                                      unsigned long long a,
                                      unsigned long long b) {
    asm("fma.rn.f32x2 %0, %1, %2, %0;" : "+l"(d) : "l"(a), "l"(b));
}
__device__ __forceinline__ void fadd2(unsigned long long& d, unsigned long long a) {
    asm("add.rn.f32x2 %0, %0, %1;" : "+l"(d) : "l"(a));
}
__device__ __forceinline__ float sum2(unsigned long long a) {
    return __uint_as_float((unsigned)a) + __uint_as_float((unsigned)(a >> 32));
}

// ============================================================
// K0: zero the accumulators (Z and pooled)
// ============================================================
__global__ void k_zero() {
    int i = blockIdx.x * blockDim.x + threadIdx.x;
    if (i < NB * NH) g_Z[i] = 0.0f;
    if (i < NB * NC) g_pooled[i] = 0.0f;
}

// ============================================================
// K1: scores s[b,t,h] = scale * <x[b,t,:], q[h,:]>  +  Z[b,h] = sum_t exp(s)
// grid (64, 32): 64 tiles of 128 rows, 32 batches. 256 threads = 8 warps.
// Each warp processes 16 rows. Lane owns c = 4*lane + 128*i (i<8).
// ============================================================
__global__ void __launch_bounds__(256, 2)
k_scores(const float* __restrict__ x, const float* __restrict__ q) {
    extern __shared__ float qs[];   // 16*1024 floats = 64 KB
    const int b    = blockIdx.y;
    const int tile = blockIdx.x;
    const int tid  = threadIdx.x;

    // stage q into smem
    for (int i = tid; i < NH * NC / 4; i += 256)
        ((float4*)qs)[i] = ((const float4*)q)[i];
    __syncthreads();

    const int warp = tid >> 5, lane = tid & 31;
    const int hh = (lane >> 1) & 15;        // head this lane owns post-reduction
    float zacc = 0.0f;

    const float* xb = x + ((size_t)b * NT) * NC;

    for (int rr = 0; rr < 16; rr++) {
        const int r = tile * 128 + warp * 16 + rr;
        const float* xr = xb + (size_t)r * NC + 4 * lane;

        // load this lane's 32 channels as 16 packed f32x2
        unsigned long long xa[8], xc[8];
        #pragma unroll
        for (int i = 0; i < 8; i++) {
            ulonglong2 v = *(const ulonglong2*)(xr + 128 * i);
            xa[i] = v.x; xc[i] = v.y;
        }

        float p[16];
        #pragma unroll
        for (int h = 0; h < 16; h++) {
            unsigned long long aA = 0ull, aB = 0ull;
            const float* qrow = qs + h * NC + 4 * lane;
            #pragma unroll
            for (int i = 0; i < 8; i++) {
                ulonglong2 qv = *(const ulonglong2*)(qrow + 128 * i);
                ffma2(aA, xa[i], qv.x);
                ffma2(aB, xc[i], qv.y);
            }
            fadd2(aA, aB);
            p[h] = sum2(aA);
        }

        // multi-value butterfly reduction: 16 vals x 32 lanes -> 16 sums
        // (16 SHFLs/row instead of 80)
#define RSTEP(M, HALF)                                                     \
        {                                                                  \
            bool up = (lane & (M)) != 0;                                   \
            _Pragma("unroll")                                              \
            for (int i = 0; i < (HALF); i++) {                             \
                float send = up ? p[i] : p[i + (HALF)];                    \
                float recv = __shfl_xor_sync(0xffffffffu, send, (M));      \
                float keep = up ? p[i + (HALF)] : p[i];                    \
                p[i] = keep + recv;                                        \
            }                                                              \
        }
        RSTEP(16, 8) RSTEP(8, 4) RSTEP(4, 2) RSTEP(2, 1)
#undef RSTEP
        float v = p[0] + __shfl_xor_sync(0xffffffffu, p[0], 1);
        v *= SCALE;

        if ((lane & 1) == 0) {
            g_scores[((size_t)b * NT + r) * NH + hh] = v;
            zacc += expf(v);
        }
    }
    if ((lane & 1) == 0)
        atomicAdd(&g_Z[b * NH + hh], zacc);
}

// ============================================================
// K2: pooled[b,c] += sum_t w[b,t]*x[b,t,c],  w = (1/16) sum_h exp(s)/Z_h
// grid (64, 32), 256 threads. Phase A: 128 threads compute w for 128 rows.
// Phase B: thread owns 4 channels, accumulates over 128 rows, atomicAdd out.
// ============================================================
__global__ void __launch_bounds__(256)
k_pool(const float* __restrict__ x) {
    __shared__ float ws[128];
    __shared__ float rz[16];
    const int b = blockIdx.y, tile = blockIdx.x, tid = threadIdx.x;

    if (tid < 16) rz[tid] = 1.0f / g_Z[b * NH + tid];
    __syncthreads();

    if (tid < 128) {
        const int r = tile * 128 + tid;
        const float4* sp = (const float4*)(g_scores + ((size_t)b * NT + r) * NH);
        float4 s0 = sp[0], s1 = sp[1], s2 = sp[2], s3 = sp[3];
        float w = expf(s0.x) * rz[0]  + expf(s0.y) * rz[1]
                + expf(s0.z) * rz[2]  + expf(s0.w) * rz[3]
                + expf(s1.x) * rz[4]  + expf(s1.y) * rz[5]
                + expf(s1.z) * rz[6]  + expf(s1.w) * rz[7]
                + expf(s2.x) * rz[8]  + expf(s2.y) * rz[9]
                + expf(s2.z) * rz[10] + expf(s2.w) * rz[11]
                + expf(s3.x) * rz[12] + expf(s3.y) * rz[13]
                + expf(s3.z) * rz[14] + expf(s3.w) * rz[15];
        ws[tid] = w * (1.0f / 16.0f);
    }
    __syncthreads();

    const int c = tid * 4;
    float4 acc = make_float4(0.f, 0.f, 0.f, 0.f);
    const float* xb = x + ((size_t)b * NT + tile * 128) * NC + c;
    #pragma unroll 4
    for (int r = 0; r < 128; r++) {
        float4 xv = *(const float4*)(xb + (size_t)r * NC);
        float w = ws[r];
        acc.x += w * xv.x; acc.y += w * xv.y;
        acc.z += w * xv.z; acc.w += w * xv.w;
    }
    float* pp = g_pooled + b * NC + c;
    atomicAdd(pp + 0, acc.x);
    atomicAdd(pp + 1, acc.y);
    atomicAdd(pp + 2, acc.z);
    atomicAdd(pp + 3, acc.w);
}

// ============================================================
// K3: out[b,j] = <pooled[b,:], W[j,:]> + bias[j]
// grid 128 CTAs x 256 threads = 8 warps; warp owns row j, loops over b.
// ============================================================
__global__ void __launch_bounds__(256)
k_proj(const float* __restrict__ w, const float* __restrict__ bias,
       float* __restrict__ out) {
    const int warp = threadIdx.x >> 5, lane = threadIdx.x & 31;
    const int j = blockIdx.x * 8 + warp;

    float4 wr[8];
    const float4* wp = (const float4*)(w + (size_t)j * NC);
    #pragma unroll
    for (int i = 0; i < 8; i++) wr[i] = wp[lane + 32 * i];
    const float bj = bias[j];

    for (int b = 0; b < NB; b++) {
        const float4* pp = (const float4*)(g_pooled + b * NC);
        float acc = 0.0f;
        #pragma unroll
        for (int i = 0; i < 8; i++) {
            float4 pv = pp[lane + 32 * i];
            acc += pv.x * wr[i].x + pv.y * wr[i].y
                 + pv.z * wr[i].z + pv.w * wr[i].w;
        }
        #pragma unroll
        for (int m = 16; m >= 1; m >>= 1)
            acc += __shfl_xor_sync(0xffffffffu, acc, m);
        if (lane == 0) out[b * NC + j] = acc + bj;
    }
}

// ============================================================
extern "C" void kernel_launch(void* const* d_in, const int* in_sizes, int n_in,
                              void* d_out, int out_size) {
    const float* x    = (const float*)d_in[0];
    const float* q    = (const float*)d_in[1];
    const float* pw   = (const float*)d_in[2];
    const float* pb   = (const float*)d_in[3];
    float* out        = (float*)d_out;

    cudaFuncSetAttribute(k_scores, cudaFuncAttributeMaxDynamicSharedMemorySize,
                         NH * NC * (int)sizeof(float));

    k_zero<<<128, 256>>>();
    k_scores<<<dim3(64, 32), 256, NH * NC * sizeof(float)>>>(x, q);
    k_pool<<<dim3(64, 32), 256>>>(x);
    k_proj<<<128, 256>>>(pw, pb, out);
}

// round 2
// speedup vs baseline: 3.6717x; 3.6717x over previous
#include <cuda_runtime.h>

#define NB 32
#define NT 8192
#define NC 1024
#define NH 16
#define SCALE 0.03125f   // 1024^-0.5

#define TILE_R 256
#define KC 16                 // channels per chunk
#define XS_STRIDE 20          // 16 + 4 pad floats -> conflict-free LDS.128
#define NCHUNK (NC / KC)      // 64

// ---- scratch (__device__ globals; allocation-free rule) ----
__device__ float g_scores[(size_t)NB * NT * NH];   // 16.8 MB
__device__ float g_Z[NB * NH];
__device__ float g_pooled[NB * NC];

// ---- packed fp32x2 (Blackwell) ----
__device__ __forceinline__ void ffma2(unsigned long long& d,
                                      unsigned long long a,
                                      unsigned long long b) {
    asm("fma.rn.f32x2 %0, %1, %2, %0;" : "+l"(d) : "l"(a), "l"(b));
}
__device__ __forceinline__ float lo2(unsigned long long a) { return __uint_as_float((unsigned)a); }
__device__ __forceinline__ float hi2(unsigned long long a) { return __uint_as_float((unsigned)(a >> 32)); }

__device__ __forceinline__ void cp16(float* dst, const float* src) {
    unsigned d = (unsigned)__cvta_generic_to_shared(dst);
    asm volatile("cp.async.ca.shared.global [%0], [%1], 16;" :: "r"(d), "l"(src));
}

// ============================================================
__global__ void k_zero() {
    int i = blockIdx.x * blockDim.x + threadIdx.x;
    if (i < NB * NH) g_Z[i] = 0.0f;
    if (i < NB * NC) g_pooled[i] = 0.0f;
}

// ============================================================
// K1: register-tiled GEMM  s[b,t,h] = scale * <x[b,t,:], q[h,:]>
// CTA: 256 rows x 16 heads. Thread: 4 rows x 4 heads, f32x2 accums
// packed over k-parity. x double-buffered via cp.async; q staged once.
// ============================================================
__global__ void __launch_bounds__(256, 2)
k_scores(const float* __restrict__ x, const float* __restrict__ q) {
    extern __shared__ float sm[];
    float* qs  = sm;                              // 16*1024 = 64 KB
    float* xs0 = sm + NH * NC;                    // 256*20 floats
    float* xs1 = xs0 + TILE_R * XS_STRIDE;
    __shared__ float zsh[NH];

    const int b = blockIdx.y, tile = blockIdx.x, tid = threadIdx.x;
    const int rowg = tid & 63, headg = tid >> 6;  // 64 row-groups x 4 head-groups

    // stage q (once)
    for (int i = tid; i < NH * NC / 4; i += 256)
        ((float4*)qs)[i] = ((const float4*)q)[i];
    if (tid < NH) zsh[tid] = 0.0f;

    const float* xb = x + ((size_t)(b * NT + tile * TILE_R)) * NC;

    // prologue: chunk 0 -> xs0 (thread tid copies row tid's 64B slice)
    {
        const float* src = xb + (size_t)tid * NC;
        float* dst = xs0 + tid * XS_STRIDE;
        #pragma unroll
        for (int g = 0; g < 4; g++) cp16(dst + 4 * g, src + 4 * g);
        asm volatile("cp.async.commit_group;");
    }

    unsigned long long acc[4][4];
    #pragma unroll
    for (int m = 0; m < 4; m++)
        #pragma unroll
        for (int h = 0; h < 4; h++) acc[m][h] = 0ull;

    for (int c = 0; c < NCHUNK; c++) {
        float* cur = (c & 1) ? xs1 : xs0;
        float* nxt = (c & 1) ? xs0 : xs1;

        if (c + 1 < NCHUNK) {
            const float* src = xb + (size_t)tid * NC + (c + 1) * KC;
            float* dst = nxt + tid * XS_STRIDE;
            #pragma unroll
            for (int g = 0; g < 4; g++) cp16(dst + 4 * g, src + 4 * g);
            asm volatile("cp.async.commit_group;");
            asm volatile("cp.async.wait_group 1;");
        } else {
            asm volatile("cp.async.wait_group 0;");
        }
        __syncthreads();

        const float* qc = qs + (size_t)headg * 4 * NC + c * KC;

        #pragma unroll
        for (int j = 0; j < 4; j++) {           // 4 channels per step
            ulonglong2 xv[4];
            #pragma unroll
            for (int m = 0; m < 4; m++)
                xv[m] = *(const ulonglong2*)(cur + (rowg + 64 * m) * XS_STRIDE + 4 * j);
            #pragma unroll
            for (int h = 0; h < 4; h++) {
                ulonglong2 qv = *(const ulonglong2*)(qc + h * NC + 4 * j); // broadcast
                #pragma unroll
                for (int m = 0; m < 4; m++) {
                    ffma2(acc[m][h], xv[m].x, qv.x);
                    ffma2(acc[m][h], xv[m].y, qv.y);
                }
            }
        }
        __syncthreads();   // buffer free before overwrite at iter c+1
    }

    // epilogue: thread owns complete sums for rows rowg+64m, heads 4*headg..+3
    float zacc[4] = {0.f, 0.f, 0.f, 0.f};
    #pragma unroll
    for (int m = 0; m < 4; m++) {
        int r = tile * TILE_R + rowg + 64 * m;
        float4 sv;
        sv.x = (lo2(acc[m][0]) + hi2(acc[m][0])) * SCALE;
        sv.y = (lo2(acc[m][1]) + hi2(acc[m][1])) * SCALE;
        sv.z = (lo2(acc[m][2]) + hi2(acc[m][2])) * SCALE;
        sv.w = (lo2(acc[m][3]) + hi2(acc[m][3])) * SCALE;
        *(float4*)(g_scores + ((size_t)b * NT + r) * NH + headg * 4) = sv;
        zacc[0] += expf(sv.x); zacc[1] += expf(sv.y);
        zacc[2] += expf(sv.z); zacc[3] += expf(sv.w);
    }
    #pragma unroll
    for (int h = 0; h < 4; h++) {
        float v = zacc[h];
        #pragma unroll
        for (int m2 = 16; m2 >= 1; m2 >>= 1)
            v += __shfl_xor_sync(0xffffffffu, v, m2);
        if ((tid & 31) == 0) atomicAdd(&zsh[headg * 4 + h], v);
    }
    __syncthreads();
    if (tid < NH) atomicAdd(&g_Z[b * NH + tid], zsh[tid]);
}

// ============================================================
// K2: pooled[b,c] += sum_t w[b,t]*x[b,t,c],  w = (1/16) sum_h exp(s)/Z_h
// ============================================================
__global__ void __launch_bounds__(256)
k_pool(const float* __restrict__ x) {
    __shared__ float ws[128];
    __shared__ float rz[16];
    const int b = blockIdx.y, tile = blockIdx.x, tid = threadIdx.x;

    if (tid < 16) rz[tid] = 1.0f / g_Z[b * NH + tid];
    __syncthreads();

    if (tid < 128) {
        const int r = tile * 128 + tid;
        const float4* sp = (const float4*)(g_scores + ((size_t)b * NT + r) * NH);
        float4 s0 = sp[0], s1 = sp[1], s2 = sp[2], s3 = sp[3];
        float w = expf(s0.x) * rz[0]  + expf(s0.y) * rz[1]
                + expf(s0.z) * rz[2]  + expf(s0.w) * rz[3]
                + expf(s1.x) * rz[4]  + expf(s1.y) * rz[5]
                + expf(s1.z) * rz[6]  + expf(s1.w) * rz[7]
                + expf(s2.x) * rz[8]  + expf(s2.y) * rz[9]
                + expf(s2.z) * rz[10] + expf(s2.w) * rz[11]
                + expf(s3.x) * rz[12] + expf(s3.y) * rz[13]
                + expf(s3.z) * rz[14] + expf(s3.w) * rz[15];
        ws[tid] = w * (1.0f / 16.0f);
    }
    __syncthreads();

    const int c = tid * 4;
    float4 acc = make_float4(0.f, 0.f, 0.f, 0.f);
    const float* xb = x + ((size_t)b * NT + tile * 128) * NC + c;
    #pragma unroll 8
    for (int r = 0; r < 128; r++) {
        float4 xv = *(const float4*)(xb + (size_t)r * NC);
        float w = ws[r];
        acc.x += w * xv.x; acc.y += w * xv.y;
        acc.z += w * xv.z; acc.w += w * xv.w;
    }
    float* pp = g_pooled + b * NC + c;
    atomicAdd(pp + 0, acc.x);
    atomicAdd(pp + 1, acc.y);
    atomicAdd(pp + 2, acc.z);
    atomicAdd(pp + 3, acc.w);
}

// ============================================================
// K3: out[b,j] = <pooled[b,:], W[j,:]> + bias[j]
// grid (128, 4): blockIdx.y picks a group of 8 batches.
// ============================================================
__global__ void __launch_bounds__(256)
k_proj(const float* __restrict__ w, const float* __restrict__ bias,
       float* __restrict__ out) {
    const int warp = threadIdx.x >> 5, lane = threadIdx.x & 31;
    const int j = blockIdx.x * 8 + warp;

    float4 wr[8];
    const float4* wp = (const float4*)(w + (size_t)j * NC);
    #pragma unroll
    for (int i = 0; i < 8; i++) wr[i] = wp[lane + 32 * i];
    const float bj = bias[j];

    const int b0 = blockIdx.y * 8;
    for (int b = b0; b < b0 + 8; b++) {
        const float4* pp = (const float4*)(g_pooled + b * NC);
        float acc = 0.0f;
        #pragma unroll
        for (int i = 0; i < 8; i++) {
            float4 pv = pp[lane + 32 * i];
            acc += pv.x * wr[i].x + pv.y * wr[i].y
                 + pv.z * wr[i].z + pv.w * wr[i].w;
        }
        #pragma unroll
        for (int m = 16; m >= 1; m >>= 1)
            acc += __shfl_xor_sync(0xffffffffu, acc, m);
        if (lane == 0) out[b * NC + j] = acc + bj;
    }
}

// ============================================================
extern "C" void kernel_launch(void* const* d_in, const int* in_sizes, int n_in,
                              void* d_out, int out_size) {
    const float* x  = (const float*)d_in[0];
    const float* q  = (const float*)d_in[1];
    const float* pw = (const float*)d_in[2];
    const float* pb = (const float*)d_in[3];
    float* out      = (float*)d_out;

    const int smem = (NH * NC + 2 * TILE_R * XS_STRIDE) * (int)sizeof(float);
    cudaFuncSetAttribute(k_scores, cudaFuncAttributeMaxDynamicSharedMemorySize, smem);

    k_zero<<<128, 256>>>();
    k_scores<<<dim3(NT / TILE_R, NB), 256, smem>>>(x, q);
    k_pool<<<dim3(64, NB), 256>>>(x);
    k_proj<<<dim3(128, 4), 256>>>(pw, pb, out);
}

// round 3
// speedup vs baseline: 6.0398x; 1.6450x over previous
#include <cuda_runtime.h>

#define NB 32
#define NT 8192
#define NC 1024
#define NH 16
#define SCALE 0.03125f   // 1024^-0.5

#define TILE_R 256
#define KC 32                  // channels per chunk (128B per row)
#define XS_STRIDE 36           // 32 + 4 pad -> conflict-free per-phase vec4
#define NCHUNK (NC / KC)       // 32

// ---- scratch (__device__ globals; allocation-free rule) ----
__device__ float g_scores[(size_t)NB * NT * NH];   // 16.8 MB
__device__ float g_Z[NB * NH];
__device__ float g_pooled[NB * NC];

// ---- packed fp32x2 (Blackwell) ----
__device__ __forceinline__ void ffma2(unsigned long long& d,
                                      unsigned long long a,
                                      unsigned long long b) {
    asm("fma.rn.f32x2 %0, %1, %2, %0;" : "+l"(d) : "l"(a), "l"(b));
}
__device__ __forceinline__ float lo2(unsigned long long a) { return __uint_as_float((unsigned)a); }
__device__ __forceinline__ float hi2(unsigned long long a) { return __uint_as_float((unsigned)(a >> 32)); }

// ============================================================
__global__ void k_zero() {
    int i = blockIdx.x * blockDim.x + threadIdx.x;
    if (i < NB * NH) g_Z[i] = 0.0f;
    if (i < NB * NC) g_pooled[i] = 0.0f;
}

// ============================================================
// K1: register-tiled GEMM  s[b,t,h] = scale * <x[b,t,:], q[h,:]>
// CTA: 256 rows x 16 heads, 256 threads, thread tile 4 rows x 4 heads.
// x staged per 32-ch chunk: LDG.128 (coalesced) -> regs -> STS.128,
// next chunk's LDGs overlap current chunk's FFMA2 compute. Single buffer.
// ============================================================
__global__ void __launch_bounds__(256, 1)
k_scores(const float* __restrict__ x, const float* __restrict__ q) {
    extern __shared__ float sm[];
    float* qs = sm;                         // 16*1024 floats = 64 KB
    float* xs = sm + NH * NC;               // 256*36 floats  = 36 KB
    __shared__ float zsh[NH];

    const int b = blockIdx.y, tile = blockIdx.x, tid = threadIdx.x;
    const int rowg = tid & 63, headg = tid >> 6;   // 64 row-groups x 4 head-groups
    const int crow = tid >> 3, ccol = (tid & 7) * 4; // copy-role: 8 lanes per row

    for (int i = tid; i < NH * NC / 4; i += 256)
        ((float4*)qs)[i] = ((const float4*)q)[i];
    if (tid < NH) zsh[tid] = 0.0f;

    const float* xb = x + ((size_t)(b * NT + tile * TILE_R)) * NC;

    float4 r[8];
#define LOADC(c)                                                            \
    _Pragma("unroll")                                                       \
    for (int g = 0; g < 8; g++)                                             \
        r[g] = *(const float4*)(xb + (size_t)(g * 32 + crow) * NC           \
                                + (c) * KC + ccol);

    LOADC(0);

    unsigned long long acc[4][4];
    #pragma unroll
    for (int m = 0; m < 4; m++)
        #pragma unroll
        for (int h = 0; h < 4; h++) acc[m][h] = 0ull;

    for (int c = 0; c < NCHUNK; c++) {
        // store regs -> smem
        #pragma unroll
        for (int g = 0; g < 8; g++)
            *(float4*)(xs + (g * 32 + crow) * XS_STRIDE + ccol) = r[g];
        __syncthreads();

        if (c + 1 < NCHUNK) { LOADC(c + 1); }   // overlap with compute below

        const float* qc = qs + (size_t)headg * 4 * NC + c * KC;
        #pragma unroll
        for (int j = 0; j < 8; j++) {           // 4 channels per step
            ulonglong2 xv[4];
            #pragma unroll
            for (int m = 0; m < 4; m++)
                xv[m] = *(const ulonglong2*)(xs + (rowg + 64 * m) * XS_STRIDE + 4 * j);
            #pragma unroll
            for (int h = 0; h < 4; h++) {
                ulonglong2 qv = *(const ulonglong2*)(qc + h * NC + 4 * j); // broadcast
                #pragma unroll
                for (int m = 0; m < 4; m++) {
                    ffma2(acc[m][h], xv[m].x, qv.x);
                    ffma2(acc[m][h], xv[m].y, qv.y);
                }
            }
        }
        __syncthreads();   // everyone done reading xs before next STS
    }
#undef LOADC

    // epilogue: thread owns complete sums for rows rowg+64m, heads 4*headg..+3
    float zacc[4] = {0.f, 0.f, 0.f, 0.f};
    #pragma unroll
    for (int m = 0; m < 4; m++) {
        int rr = tile * TILE_R + rowg + 64 * m;
        float4 sv;
        sv.x = (lo2(acc[m][0]) + hi2(acc[m][0])) * SCALE;
        sv.y = (lo2(acc[m][1]) + hi2(acc[m][1])) * SCALE;
        sv.z = (lo2(acc[m][2]) + hi2(acc[m][2])) * SCALE;
        sv.w = (lo2(acc[m][3]) + hi2(acc[m][3])) * SCALE;
        *(float4*)(g_scores + ((size_t)b * NT + rr) * NH + headg * 4) = sv;
        zacc[0] += expf(sv.x); zacc[1] += expf(sv.y);
        zacc[2] += expf(sv.z); zacc[3] += expf(sv.w);
    }
    #pragma unroll
    for (int h = 0; h < 4; h++) {
        float v = zacc[h];
        #pragma unroll
        for (int m2 = 16; m2 >= 1; m2 >>= 1)
            v += __shfl_xor_sync(0xffffffffu, v, m2);
        if ((tid & 31) == 0) atomicAdd(&zsh[headg * 4 + h], v);
    }
    __syncthreads();
    if (tid < NH) atomicAdd(&g_Z[b * NH + tid], zsh[tid]);
}

// ============================================================
// K2: pooled[b,c] += sum_t w[b,t]*x[b,t,c],  w = (1/16) sum_h exp(s)/Z_h
// ============================================================
__global__ void __launch_bounds__(256)
k_pool(const float* __restrict__ x) {
    __shared__ float ws[128];
    __shared__ float rz[16];
    const int b = blockIdx.y, tile = blockIdx.x, tid = threadIdx.x;

    if (tid < 16) rz[tid] = 1.0f / g_Z[b * NH + tid];
    __syncthreads();

    if (tid < 128) {
        const int r = tile * 128 + tid;
        const float4* sp = (const float4*)(g_scores + ((size_t)b * NT + r) * NH);
        float4 s0 = sp[0], s1 = sp[1], s2 = sp[2], s3 = sp[3];
        float w = expf(s0.x) * rz[0]  + expf(s0.y) * rz[1]
                + expf(s0.z) * rz[2]  + expf(s0.w) * rz[3]
                + expf(s1.x) * rz[4]  + expf(s1.y) * rz[5]
                + expf(s1.z) * rz[6]  + expf(s1.w) * rz[7]
                + expf(s2.x) * rz[8]  + expf(s2.y) * rz[9]
                + expf(s2.z) * rz[10] + expf(s2.w) * rz[11]
                + expf(s3.x) * rz[12] + expf(s3.y) * rz[13]
                + expf(s3.z) * rz[14] + expf(s3.w) * rz[15];
        ws[tid] = w * (1.0f / 16.0f);
    }
    __syncthreads();

    const int c = tid * 4;
    float4 acc = make_float4(0.f, 0.f, 0.f, 0.f);
    const float* xb = x + ((size_t)b * NT + tile * 128) * NC + c;
    #pragma unroll 8
    for (int r = 0; r < 128; r++) {
        float4 xv = *(const float4*)(xb + (size_t)r * NC);
        float w = ws[r];
        acc.x += w * xv.x; acc.y += w * xv.y;
        acc.z += w * xv.z; acc.w += w * xv.w;
    }
    float* pp = g_pooled + b * NC + c;
    atomicAdd(pp + 0, acc.x);
    atomicAdd(pp + 1, acc.y);
    atomicAdd(pp + 2, acc.z);
    atomicAdd(pp + 3, acc.w);
}

// ============================================================
// K3: out[b,j] = <pooled[b,:], W[j,:]> + bias[j]
// ============================================================
__global__ void __launch_bounds__(256)
k_proj(const float* __restrict__ w, const float* __restrict__ bias,
       float* __restrict__ out) {
    const int warp = threadIdx.x >> 5, lane = threadIdx.x & 31;
    const int j = blockIdx.x * 8 + warp;

    float4 wr[8];
    const float4* wp = (const float4*)(w + (size_t)j * NC);
    #pragma unroll
    for (int i = 0; i < 8; i++) wr[i] = wp[lane + 32 * i];
    const float bj = bias[j];

    const int b0 = blockIdx.y * 8;
    for (int b = b0; b < b0 + 8; b++) {
        const float4* pp = (const float4*)(g_pooled + b * NC);
        float acc = 0.0f;
        #pragma unroll
        for (int i = 0; i < 8; i++) {
            float4 pv = pp[lane + 32 * i];
            acc += pv.x * wr[i].x + pv.y * wr[i].y
                 + pv.z * wr[i].z + pv.w * wr[i].w;
        }
        #pragma unroll
        for (int m = 16; m >= 1; m >>= 1)
            acc += __shfl_xor_sync(0xffffffffu, acc, m);
        if (lane == 0) out[b * NC + j] = acc + bj;
    }
}

// ============================================================
extern "C" void kernel_launch(void* const* d_in, const int* in_sizes, int n_in,
                              void* d_out, int out_size) {
    const float* x  = (const float*)d_in[0];
    const float* q  = (const float*)d_in[1];
    const float* pw = (const float*)d_in[2];
    const float* pb = (const float*)d_in[3];
    float* out      = (float*)d_out;

    const int smem = (NH * NC + TILE_R * XS_STRIDE) * (int)sizeof(float);
    cudaFuncSetAttribute(k_scores, cudaFuncAttributeMaxDynamicSharedMemorySize, smem);

    k_zero<<<128, 256>>>();
    k_scores<<<dim3(NT / TILE_R, NB), 256, smem>>>(x, q);
    k_pool<<<dim3(64, NB), 256>>>(x);
    k_proj<<<dim3(128, 4), 256>>>(pw, pb, out);
}

// round 4
// speedup vs baseline: 6.3338x; 1.0487x over previous
#include <cuda_runtime.h>

#define NB 32
#define NT 8192
#define NC 1024
#define NH 16
#define SCALE 0.03125f   // 1024^-0.5

#define TILE_R 256
#define KC 16                  // channels per chunk (64B per row)
#define XS_STRIDE 20           // 16 + 4 pad -> conflict-free 8-lane phases
#define NCHUNK (NC / KC)       // 64

// ---- scratch (__device__ globals; allocation-free rule) ----
__device__ float g_scores[(size_t)NB * NT * NH];   // 16.8 MB
__device__ float g_Z[NB * NH];
__device__ float g_pooled[NB * NC];

// ---- packed fp32x2 (Blackwell) ----
__device__ __forceinline__ void ffma2(unsigned long long& d,
                                      unsigned long long a,
                                      unsigned long long b) {
    asm("fma.rn.f32x2 %0, %1, %2, %0;" : "+l"(d) : "l"(a), "l"(b));
}
__device__ __forceinline__ float lo2(unsigned long long a) { return __uint_as_float((unsigned)a); }
__device__ __forceinline__ float hi2(unsigned long long a) { return __uint_as_float((unsigned)(a >> 32)); }

// ============================================================
__global__ void k_zero() {
    int i = blockIdx.x * blockDim.x + threadIdx.x;
    if (i < NB * NH) g_Z[i] = 0.0f;
    if (i < NB * NC) g_pooled[i] = 0.0f;
}

// ============================================================
// K1: register-tiled GEMM  s[b,t,h] = scale * <x[b,t,:], q[h,:]>
// CTA: 256 rows x 16 heads, 128 threads = 64 rowg x 2 headg.
// Thread tile: 4 rows x 8 heads (f32x2 accums over channel parity).
// Per j-step: 4 full-wavefront xv LDS.128 + 8 broadcast qv LDS.128
// per 64 FFMA2 -> crossbar no longer the 2x bottleneck.
// ============================================================
__global__ void __launch_bounds__(128, 2)
k_scores(const float* __restrict__ x, const float* __restrict__ q) {
    extern __shared__ float sm[];
    float* qs = sm;                         // 16*1024 floats = 64 KB
    float* xs = sm + NH * NC;               // 256*20 floats  = 20 KB
    __shared__ float zsh[NH];

    const int b = blockIdx.y, tile = blockIdx.x, tid = threadIdx.x;
    const int rowg = tid & 63, headg = tid >> 6;      // 64 x 2
    const int crow = tid >> 2, ccol = (tid & 3) * 4;  // copy: 4 lanes per row

    for (int i = tid; i < NH * NC / 4; i += 128)
        ((float4*)qs)[i] = ((const float4*)q)[i];
    if (tid < NH) zsh[tid] = 0.0f;

    const float* xb = x + ((size_t)(b * NT + tile * TILE_R)) * NC;

    float4 r[8];
#define LOADC(c)                                                            \
    _Pragma("unroll")                                                       \
    for (int g = 0; g < 8; g++)                                             \
        r[g] = *(const float4*)(xb + (size_t)(g * 32 + crow) * NC           \
                                + (c) * KC + ccol);

    LOADC(0);

    unsigned long long acc[4][8];
    #pragma unroll
    for (int m = 0; m < 4; m++)
        #pragma unroll
        for (int h = 0; h < 8; h++) acc[m][h] = 0ull;

    for (int c = 0; c < NCHUNK; c++) {
        #pragma unroll
        for (int g = 0; g < 8; g++)
            *(float4*)(xs + (g * 32 + crow) * XS_STRIDE + ccol) = r[g];
        __syncthreads();

        if (c + 1 < NCHUNK) { LOADC(c + 1); }   // LDGs overlap compute

        const float* qc = qs + (size_t)headg * 8 * NC + c * KC;
        #pragma unroll
        for (int j = 0; j < 4; j++) {           // 4 channels per step
            ulonglong2 xv[4];
            #pragma unroll
            for (int m = 0; m < 4; m++)
                xv[m] = *(const ulonglong2*)(xs + (rowg + 64 * m) * XS_STRIDE + 4 * j);
            #pragma unroll
            for (int h = 0; h < 8; h++) {
                ulonglong2 qv = *(const ulonglong2*)(qc + h * NC + 4 * j); // broadcast
                #pragma unroll
                for (int m = 0; m < 4; m++) {
                    ffma2(acc[m][h], xv[m].x, qv.x);
                    ffma2(acc[m][h], xv[m].y, qv.y);
                }
            }
        }
        __syncthreads();   // readers done before next STS
    }
#undef LOADC

    // epilogue: thread owns rows rowg+64m, heads headg*8 .. headg*8+7
    float zacc[8];
    #pragma unroll
    for (int h = 0; h < 8; h++) zacc[h] = 0.0f;

    #pragma unroll
    for (int m = 0; m < 4; m++) {
        int rr = tile * TILE_R + rowg + 64 * m;
        float s[8];
        #pragma unroll
        for (int h = 0; h < 8; h++) {
            s[h] = (lo2(acc[m][h]) + hi2(acc[m][h])) * SCALE;
            zacc[h] += expf(s[h]);
        }
        float* dst = g_scores + ((size_t)b * NT + rr) * NH + headg * 8;
        *(float4*)(dst + 0) = make_float4(s[0], s[1], s[2], s[3]);
        *(float4*)(dst + 4) = make_float4(s[4], s[5], s[6], s[7]);
    }
    #pragma unroll
    for (int h = 0; h < 8; h++) {
        float v = zacc[h];
        #pragma unroll
        for (int m2 = 16; m2 >= 1; m2 >>= 1)
            v += __shfl_xor_sync(0xffffffffu, v, m2);
        if ((tid & 31) == 0) atomicAdd(&zsh[headg * 8 + h], v);
    }
    __syncthreads();
    if (tid < NH) atomicAdd(&g_Z[b * NH + tid], zsh[tid]);
}

// ============================================================
// K2: pooled[b,c] += sum_t w[b,t]*x[b,t,c],  w = (1/16) sum_h exp(s)/Z_h
// ============================================================
__global__ void __launch_bounds__(256)
k_pool(const float* __restrict__ x) {
    __shared__ float ws[128];
    __shared__ float rz[16];
    const int b = blockIdx.y, tile = blockIdx.x, tid = threadIdx.x;

    if (tid < 16) rz[tid] = 1.0f / g_Z[b * NH + tid];
    __syncthreads();

    if (tid < 128) {
        const int r = tile * 128 + tid;
        const float4* sp = (const float4*)(g_scores + ((size_t)b * NT + r) * NH);
        float4 s0 = sp[0], s1 = sp[1], s2 = sp[2], s3 = sp[3];
        float w = expf(s0.x) * rz[0]  + expf(s0.y) * rz[1]
                + expf(s0.z) * rz[2]  + expf(s0.w) * rz[3]
                + expf(s1.x) * rz[4]  + expf(s1.y) * rz[5]
                + expf(s1.z) * rz[6]  + expf(s1.w) * rz[7]
                + expf(s2.x) * rz[8]  + expf(s2.y) * rz[9]
                + expf(s2.z) * rz[10] + expf(s2.w) * rz[11]
                + expf(s3.x) * rz[12] + expf(s3.y) * rz[13]
                + expf(s3.z) * rz[14] + expf(s3.w) * rz[15];
        ws[tid] = w * (1.0f / 16.0f);
    }
    __syncthreads();

    const int c = tid * 4;
    float4 acc = make_float4(0.f, 0.f, 0.f, 0.f);
    const float* xb = x + ((size_t)b * NT + tile * 128) * NC + c;
    #pragma unroll 8
    for (int r = 0; r < 128; r++) {
        float4 xv = *(const float4*)(xb + (size_t)r * NC);
        float w = ws[r];
        acc.x += w * xv.x; acc.y += w * xv.y;
        acc.z += w * xv.z; acc.w += w * xv.w;
    }
    float* pp = g_pooled + b * NC + c;
    atomicAdd(pp + 0, acc.x);
    atomicAdd(pp + 1, acc.y);
    atomicAdd(pp + 2, acc.z);
    atomicAdd(pp + 3, acc.w);
}

// ============================================================
// K3: out[b,j] = <pooled[b,:], W[j,:]> + bias[j]
// ============================================================
__global__ void __launch_bounds__(256)
k_proj(const float* __restrict__ w, const float* __restrict__ bias,
       float* __restrict__ out) {
    const int warp = threadIdx.x >> 5, lane = threadIdx.x & 31;
    const int j = blockIdx.x * 8 + warp;

    float4 wr[8];
    const float4* wp = (const float4*)(w + (size_t)j * NC);
    #pragma unroll
    for (int i = 0; i < 8; i++) wr[i] = wp[lane + 32 * i];
    const float bj = bias[j];

    const int b0 = blockIdx.y * 8;
    for (int b = b0; b < b0 + 8; b++) {
        const float4* pp = (const float4*)(g_pooled + b * NC);
        float acc = 0.0f;
        #pragma unroll
        for (int i = 0; i < 8; i++) {
            float4 pv = pp[lane + 32 * i];
            acc += pv.x * wr[i].x + pv.y * wr[i].y
                 + pv.z * wr[i].z + pv.w * wr[i].w;
        }
        #pragma unroll
        for (int m = 16; m >= 1; m >>= 1)
            acc += __shfl_xor_sync(0xffffffffu, acc, m);
        if (lane == 0) out[b * NC + j] = acc + bj;
    }
}

// ============================================================
extern "C" void kernel_launch(void* const* d_in, const int* in_sizes, int n_in,
                              void* d_out, int out_size) {
    const float* x  = (const float*)d_in[0];
    const float* q  = (const float*)d_in[1];
    const float* pw = (const float*)d_in[2];
    const float* pb = (const float*)d_in[3];
    float* out      = (float*)d_out;

    const int smem = (NH * NC + TILE_R * XS_STRIDE) * (int)sizeof(float);
    cudaFuncSetAttribute(k_scores, cudaFuncAttributeMaxDynamicSharedMemorySize, smem);

    k_zero<<<128, 256>>>();
    k_scores<<<dim3(NT / TILE_R, NB), 128, smem>>>(x, q);
    k_pool<<<dim3(64, NB), 256>>>(x);
    k_proj<<<dim3(128, 4), 256>>>(pw, pb, out);
}